// round 5
// baseline (speedup 1.0000x reference)
#include <cuda_runtime.h>
#include <math.h>

#define NROWS  262144
#define NCTA   4096          // 128 threads each -> 16384 warps, 16 rows/warp
#define NWARPS 16384

// Unified per-block weights, packed for f32x2 FMA.
// g_Wraw[lane*64 + o*16 + dp*2 + half] = M[j][2*dp+half][q*4+o]
// lane = 4*j + q (j=block, q=output quad), o = output within quad,
// d = 2*dp+half. Consecutive float pairs form one 64-bit f32x2 operand.
__device__ float g_Wraw[32 * 4 * 8 * 2];

__global__ void bdla_prep(const float* __restrict__ W,
                          const float* __restrict__ s,
                          const float* __restrict__ U,
                          const float* __restrict__ V) {
    int e = threadIdx.x + blockIdx.x * blockDim.x;
    if (e >= 2048) return;
    int half = e & 1;
    int dp   = (e >> 1) & 7;
    int o    = (e >> 4) & 3;
    int lane = e >> 6;
    int j = lane >> 2, q = lane & 3;
    int d  = 2 * dp + half;
    int ob = q * 4 + o;
    float val;
    if (j == 0 || j == 3 || j == 6) {            // dense: y = x @ W^T
        int k = j / 3;
        val = W[k * 256 + ob * 16 + d];
    } else if (j == 1 || j == 4 || j == 7) {     // diagonal
        int k = (j - 1) / 3;
        val = (d == ob) ? s[k * 16 + d] : 0.0f;
    } else {                                     // lowrank: (V U^T)[d][ob]
        int k = (j - 2) / 3;
        float acc = 0.0f;
        #pragma unroll
        for (int r = 0; r < 4; ++r)
            acc += V[k * 64 + d * 4 + r] * U[k * 64 + ob * 4 + r];
        val = acc;
    }
    g_Wraw[e] = val;
}

typedef unsigned long long ull;

__device__ __forceinline__ ull pk(float a, float b) {
    ull r; asm("mov.b64 %0, {%1,%2};" : "=l"(r) : "f"(a), "f"(b)); return r;
}
__device__ __forceinline__ void upk(ull p, float& a, float& b) {
    asm("mov.b64 {%0,%1}, %2;" : "=f"(a), "=f"(b) : "l"(p));
}
__device__ __forceinline__ ull ff2(ull a, ull b, ull c) {
    ull d; asm("fma.rn.f32x2 %0, %1, %2, %3;" : "=l"(d) : "l"(a), "l"(b), "l"(c));
    return d;
}

// Per-row math, shared by both unrolled copies.
__device__ __forceinline__ void row_compute(const float4 xv, const ull* wp,
                                            int lane, float4* outp) {
    ull acc0 = 0ull, acc1 = 0ull, acc2 = 0ull, acc3 = 0ull;
    #pragma unroll
    for (int sb = 0; sb < 4; ++sb) {
        const int src = (lane & 28) + sb;
        const float a0 = __shfl_sync(0xffffffffu, xv.x, src);
        const float a1 = __shfl_sync(0xffffffffu, xv.y, src);
        const float a2 = __shfl_sync(0xffffffffu, xv.z, src);
        const float a3 = __shfl_sync(0xffffffffu, xv.w, src);
        const ull p0 = pk(a0, a1);
        const ull p1 = pk(a2, a3);
        const int dp = 2 * sb;
        acc0 = ff2(p0, wp[0  + dp], acc0); acc0 = ff2(p1, wp[1  + dp], acc0);
        acc1 = ff2(p0, wp[8  + dp], acc1); acc1 = ff2(p1, wp[9  + dp], acc1);
        acc2 = ff2(p0, wp[16 + dp], acc2); acc2 = ff2(p1, wp[17 + dp], acc2);
        acc3 = ff2(p0, wp[24 + dp], acc3); acc3 = ff2(p1, wp[25 + dp], acc3);
    }
    float l0, h0, l1, h1, l2, h2, l3, h3;
    upk(acc0, l0, h0); upk(acc1, l1, h1);
    upk(acc2, l2, h2); upk(acc3, l3, h3);
    const float y0 = l0 + h0, y1 = l1 + h1, y2 = l2 + h2, y3 = l3 + h3;

    float ss = y0 * y0;
    ss = fmaf(y1, y1, ss); ss = fmaf(y2, y2, ss); ss = fmaf(y3, y3, ss);
    #pragma unroll
    for (int m = 16; m >= 1; m >>= 1)
        ss += __shfl_xor_sync(0xffffffffu, ss, m);
    const float inv = __fdividef(1.0f, sqrtf(ss) + 1e-8f);

    *outp = make_float4(y0 * inv, y1 * inv, y2 * inv, y3 * inv);
}

__global__ void __launch_bounds__(128, 5)
bdla_main(const float4* __restrict__ x, float4* __restrict__ y) {
    const int lane = threadIdx.x & 31;
    const int gw   = (blockIdx.x * 128 + threadIdx.x) >> 5;

    // 32 packed weight pairs = 64 regs; loaded once per warp (L2-resident).
    ull wp[32];
    {
        const ull* wsrc = ((const ull*)g_Wraw) + lane * 32;
        #pragma unroll
        for (int i = 0; i < 32; ++i) wp[i] = wsrc[i];
    }

    #pragma unroll 1
    for (int it = 0; it < NROWS / (NWARPS * 2); ++it) {
        const unsigned r0 = (unsigned)gw + (unsigned)(it * 2) * NWARPS;
        const unsigned r1 = r0 + NWARPS;

        // Front-batch both row loads (scalar vars, not arrays -> no spills).
        const float4 xa = x[r0 * 32u + lane];
        const float4 xb = x[r1 * 32u + lane];

        row_compute(xa, wp, lane, &((float4*)y)[r0 * 32u + lane]);
        row_compute(xb, wp, lane, &((float4*)y)[r1 * 32u + lane]);
    }
}

extern "C" void kernel_launch(void* const* d_in, const int* in_sizes, int n_in,
                              void* d_out, int out_size) {
    const float* x = (const float*)d_in[0];
    const float* W = (const float*)d_in[1];
    const float* s = (const float*)d_in[2];
    const float* U = (const float*)d_in[3];
    const float* V = (const float*)d_in[4];
    float* out = (float*)d_out;

    bdla_prep<<<8, 256>>>(W, s, U, V);
    bdla_main<<<NCTA, 128>>>((const float4*)x, (float4*)out);
}

// round 6
// speedup vs baseline: 2.5455x; 2.5455x over previous
#include <cuda_runtime.h>
#include <math.h>
#include <stdint.h>

#define NROWS   262144
#define NCTA    2048
#define ROWS_PER_CTA (NROWS / NCTA)   // 128
#define TILE_R  16                    // rows per pipeline stage (8 KB)
#define STAGES  4
#define NT      (ROWS_PER_CTA / TILE_R) // 8 tiles per CTA

// Unified per-block 16x16 matrices (R1 layout, proven):
// g_M4[j*64 + d*4 + q] = M[j][d][4q..4q+3]
__device__ float4 g_M4[8 * 16 * 4];

__global__ void bdla_prep(const float* __restrict__ W,
                          const float* __restrict__ s,
                          const float* __restrict__ U,
                          const float* __restrict__ V) {
    float* gm = (float*)g_M4;
    for (int e = threadIdx.x + blockIdx.x * blockDim.x; e < 8 * 16 * 16;
         e += blockDim.x * gridDim.x) {
        int j = e >> 8;
        int rem = e & 255;
        int d = rem >> 4;
        int o = rem & 15;
        float val;
        if (j == 0 || j == 3 || j == 6) {            // dense: y = x @ W^T
            int k = j / 3;
            val = W[k * 256 + o * 16 + d];
        } else if (j == 1 || j == 4 || j == 7) {     // diagonal
            int k = (j - 1) / 3;
            val = (d == o) ? s[k * 16 + d] : 0.0f;
        } else {                                     // lowrank: (V U^T)[d][o]
            int k = (j - 2) / 3;
            float acc = 0.0f;
            #pragma unroll
            for (int r = 0; r < 4; ++r)
                acc += V[k * 64 + d * 4 + r] * U[k * 64 + o * 4 + r];
            val = acc;
        }
        gm[j * 256 + d * 16 + o] = val;
    }
}

__device__ __forceinline__ void cpa16(uint32_t dst, const float4* src) {
    asm volatile("cp.async.cg.shared.global [%0], [%1], 16;"
                 :: "r"(dst), "l"(src));
}
__device__ __forceinline__ void cpa_commit() {
    asm volatile("cp.async.commit_group;");
}
__device__ __forceinline__ void cpa_wait3() {
    asm volatile("cp.async.wait_group 3;");
}

__global__ void __launch_bounds__(128)
bdla_main(const float4* __restrict__ x, float4* __restrict__ y) {
    __shared__ float4 sx[STAGES][TILE_R * 32];   // 4 x 8 KB = 32 KB

    const int tid  = threadIdx.x;
    const int lane = tid & 31;
    const int wid  = tid >> 5;                   // 0..3
    const int j    = lane >> 2;                  // block id
    const int q    = lane & 3;                   // output quad
    const unsigned ctaRow0 = blockIdx.x * ROWS_PER_CTA;

    // 64 weight registers, loaded once (L2-resident after first wave).
    float4 w[16];
    {
        const float4* Mp = g_M4 + (j << 6) + q;
        #pragma unroll
        for (int d = 0; d < 16; ++d) w[d] = Mp[d * 4];
    }

    const float4* gsrc0 = x + (size_t)ctaRow0 * 32;
    const uint32_t sbase = (uint32_t)__cvta_generic_to_shared(&sx[0][0]);

    // Prologue: prefetch tiles 0..STAGES-2 (3 tiles, one commit group each).
    #pragma unroll
    for (int t = 0; t < STAGES - 1; ++t) {
        const uint32_t dst0 = sbase + (uint32_t)(t * TILE_R * 512);
        const float4* src0 = gsrc0 + t * TILE_R * 32;
        #pragma unroll
        for (int i = 0; i < 4; ++i)
            cpa16(dst0 + (tid + 128 * i) * 16u, src0 + tid + 128 * i);
        cpa_commit();
    }

    #pragma unroll 1
    for (int t = 0; t < NT; ++t) {
        // Issue tile t+STAGES-1 (empty commit group past the end keeps the
        // group sequence aligned for wait_group).
        const int tp = t + STAGES - 1;
        if (tp < NT) {
            const uint32_t dst0 = sbase + (uint32_t)((tp & (STAGES - 1)) * TILE_R * 512);
            const float4* src0 = gsrc0 + tp * TILE_R * 32;
            #pragma unroll
            for (int i = 0; i < 4; ++i)
                cpa16(dst0 + (tid + 128 * i) * 16u, src0 + tid + 128 * i);
        }
        cpa_commit();

        cpa_wait3();              // tile t's group complete (<=3 pending)
        __syncthreads();          // visible to all warps

        const float4* tile = &sx[t & (STAGES - 1)][0];

        // Each warp computes 4 rows of the 16-row tile.
        #pragma unroll
        for (int k = 0; k < 4; ++k) {
            const int rit = wid + 4 * k;
            const float4* rowp = tile + rit * 32 + j * 4;

            float y0 = 0.f, y1 = 0.f, y2 = 0.f, y3 = 0.f;
            #pragma unroll
            for (int sb = 0; sb < 4; ++sb) {
                const float4 a = rowp[sb];           // LDS.128, quad-broadcast
                const float4 w0 = w[4 * sb + 0];
                const float4 w1 = w[4 * sb + 1];
                const float4 w2 = w[4 * sb + 2];
                const float4 w3 = w[4 * sb + 3];
                y0 = fmaf(a.x, w0.x, y0); y1 = fmaf(a.x, w0.y, y1);
                y2 = fmaf(a.x, w0.z, y2); y3 = fmaf(a.x, w0.w, y3);
                y0 = fmaf(a.y, w1.x, y0); y1 = fmaf(a.y, w1.y, y1);
                y2 = fmaf(a.y, w1.z, y2); y3 = fmaf(a.y, w1.w, y3);
                y0 = fmaf(a.z, w2.x, y0); y1 = fmaf(a.z, w2.y, y1);
                y2 = fmaf(a.z, w2.z, y2); y3 = fmaf(a.z, w2.w, y3);
                y0 = fmaf(a.w, w3.x, y0); y1 = fmaf(a.w, w3.y, y1);
                y2 = fmaf(a.w, w3.z, y2); y3 = fmaf(a.w, w3.w, y3);
            }

            // Row L2 norm across all 32 lanes (one row per warp).
            float ss = y0 * y0;
            ss = fmaf(y1, y1, ss); ss = fmaf(y2, y2, ss); ss = fmaf(y3, y3, ss);
            #pragma unroll
            for (int m = 16; m >= 1; m >>= 1)
                ss += __shfl_xor_sync(0xffffffffu, ss, m);
            const float inv = rsqrtf(ss);

            const unsigned grow = ctaRow0 + (unsigned)(t * TILE_R + rit);
            y[(size_t)grow * 32 + lane] =
                make_float4(y0 * inv, y1 * inv, y2 * inv, y3 * inv);
        }

        __syncthreads();          // stage reused by the issue at t+1
    }
}

extern "C" void kernel_launch(void* const* d_in, const int* in_sizes, int n_in,
                              void* d_out, int out_size) {
    const float* x = (const float*)d_in[0];
    const float* W = (const float*)d_in[1];
    const float* s = (const float*)d_in[2];
    const float* U = (const float*)d_in[3];
    const float* V = (const float*)d_in[4];
    float* out = (float*)d_out;

    bdla_prep<<<8, 256>>>(W, s, U, V);
    bdla_main<<<NCTA, 128>>>((const float4*)x, (float4*)out);
}